// round 13
// baseline (speedup 1.0000x reference)
#include <cuda_runtime.h>
#include <cuda_bf16.h>
#include <math.h>
#include <cstdint>

// Problem constants (fixed shapes)
#define B 4
#define S 512
#define T 256
#define H 1024
#define V 32000
#define M1 (B * S)   // 2048

// Scratch (device globals — no allocations allowed)
__device__ float g_scores[B * T * S];        // [b][t][s], 2 MB
__device__ unsigned short g_Eh[M1 * H];      // bf16 hi of E   [M,K]
__device__ unsigned short g_El[M1 * H];      // bf16 lo of E   [M,K]
__device__ unsigned short g_Wh[H * H];       // bf16 hi of W^T [N,K]
__device__ unsigned short g_Wl[H * H];       // bf16 lo of W^T [N,K]
__device__ unsigned short g_Ench[B * S * H]; // bf16 hi of enc [b][s][h]
__device__ unsigned short g_Encl[B * S * H]; // bf16 lo of enc [b][s][h]
__device__ unsigned short g_Dech[B * T * H]; // bf16 hi of dec [b][t][h]
__device__ unsigned short g_Decl[B * T * H]; // bf16 lo of dec [b][t][h]

// ---------------------------------------------------------------------------
// Arch-generic tensor-core primitives (legal on plain sm_103 target)
// ---------------------------------------------------------------------------
#define LDSM4(r, a)                                                            \
    asm volatile("ldmatrix.sync.aligned.m8n8.x4.shared.b16 {%0,%1,%2,%3}, [%4];" \
        : "=r"((r)[0]), "=r"((r)[1]), "=r"((r)[2]), "=r"((r)[3]) : "r"(a))

#define MMA_BF16(d, a, b0, b1)                                                 \
    asm volatile(                                                              \
        "mma.sync.aligned.m16n8k16.row.col.f32.bf16.bf16.f32 "                 \
        "{%0,%1,%2,%3}, {%4,%5,%6,%7}, {%8,%9}, {%0,%1,%2,%3};"                \
        : "+f"((d)[0]), "+f"((d)[1]), "+f"((d)[2]), "+f"((d)[3])               \
        : "r"((a)[0]), "r"((a)[1]), "r"((a)[2]), "r"((a)[3]),                  \
          "r"(b0), "r"(b1))

__device__ __forceinline__ uint32_t smem_to_u32(const void* p) {
    uint32_t a;
    asm("{ .reg .u64 t; cvta.to.shared.u64 t, %1; cvt.u32.u64 %0, t; }"
        : "=r"(a) : "l"(p));
    return a;
}

__device__ __forceinline__ void split_store2(
    unsigned short* hp, unsigned short* lp, float v0, float v1)
{
    __nv_bfloat16 h0 = __float2bfloat16_rn(v0);
    __nv_bfloat16 h1 = __float2bfloat16_rn(v1);
    unsigned short l0 = __bfloat16_as_ushort(__float2bfloat16_rn(v0 - __bfloat162float(h0)));
    unsigned short l1 = __bfloat16_as_ushort(__float2bfloat16_rn(v1 - __bfloat162float(h1)));
    *(uint32_t*)hp = (uint32_t)__bfloat16_as_ushort(h0) |
                     ((uint32_t)__bfloat16_as_ushort(h1) << 16);
    *(uint32_t*)lp = (uint32_t)l0 | ((uint32_t)l1 << 16);
}

// ---------------------------------------------------------------------------
// Converter: E and Dec fp32 -> bf16 hi/lo in ONE kernel.
// ---------------------------------------------------------------------------
#define E_F4 (M1 * H / 4)          // 524288
#define D_F4 (B * T * H / 4)       // 262144

__global__ __launch_bounds__(256) void convert_splits(
    const float* __restrict__ E, const float* __restrict__ Dec)
{
    const int idx = blockIdx.x * 256 + threadIdx.x;
    const float* src;
    unsigned short *hi, *lo;
    int j;
    if (idx < E_F4) {
        src = E; hi = g_Eh; lo = g_El; j = idx;
    } else {
        src = Dec; hi = g_Dech; lo = g_Decl; j = idx - E_F4;
    }
    const float4 v = ((const float4*)src)[j];
    ushort4 h, l;
    const float* vf = (const float*)&v;
    unsigned short* hp = (unsigned short*)&h;
    unsigned short* lp = (unsigned short*)&l;
#pragma unroll
    for (int i = 0; i < 4; i++) {
        __nv_bfloat16 hb = __float2bfloat16_rn(vf[i]);
        hp[i] = __bfloat16_as_ushort(hb);
        lp[i] = __bfloat16_as_ushort(__float2bfloat16_rn(vf[i] - __bfloat162float(hb)));
    }
    ((ushort4*)hi)[j] = h;
    ((ushort4*)lo)[j] = l;
}

__global__ __launch_bounds__(256) void convert_W(const float* __restrict__ W)
{
    __shared__ float t[32][33];
    const int k0 = blockIdx.x * 32;
    const int n0 = blockIdx.y * 32;
    const int tx = threadIdx.x & 31;
    const int ty = threadIdx.x >> 5;
#pragma unroll
    for (int r = 0; r < 4; r++) {
        const int k = ty + r * 8;
        t[k][tx] = W[(size_t)(k0 + k) * H + n0 + tx];
    }
    __syncthreads();
#pragma unroll
    for (int r = 0; r < 4; r++) {
        const int n = ty + r * 8;
        const float x = t[tx][n];
        __nv_bfloat16 hb = __float2bfloat16_rn(x);
        g_Wh[(size_t)(n0 + n) * H + k0 + tx] = __bfloat16_as_ushort(hb);
        g_Wl[(size_t)(n0 + n) * H + k0 + tx] =
            __bfloat16_as_ushort(__float2bfloat16_rn(x - __bfloat162float(hb)));
    }
}

// ---------------------------------------------------------------------------
// GEMM1 (R10/R12 config — 48.7us, established floor for this path):
// CTA 128x128, BK=32, 2-stage cp.async, 64 KB dyn smem,
// 8 warps = 4(M) x 2(N), warp 32x64, hi/lo 3-pass.
// ---------------------------------------------------------------------------
#define BK1 32
#define TILE_B (128 * 64)         // 8 KB per tile
#define STAGE_B (4 * TILE_B)      // Ah, Al, Bh, Bl = 32 KB
#define SMEM_G1 (2 * STAGE_B)     // 64 KB

__global__ __launch_bounds__(256, 1) void gemm1_mma(const float* __restrict__ bias)
{
    extern __shared__ __align__(128) char smem[];
    const uint32_t sb = smem_to_u32(smem);
    const int tid = threadIdx.x;
    const int lane = tid & 31;
    const int wid = tid >> 5;
    const int wm = wid & 3;           // 0..3 (M)
    const int wn = wid >> 2;          // 0..1 (N)
    const int bm = blockIdx.y * 128;  // (b,s) tile
    const int bn = blockIdx.x * 128;  // h tile

    const unsigned short* srcs[4] = {g_Eh, g_El, g_Wh, g_Wl};

    float acc[2][8][4];
#pragma unroll
    for (int mt = 0; mt < 2; mt++)
#pragma unroll
        for (int nt = 0; nt < 8; nt++)
#pragma unroll
            for (int q = 0; q < 4; q++) acc[mt][nt][q] = 0.f;

    const int arow = lane & 15;
    const int half = lane >> 4;

#define G1_ISSUE(ch, stage)                                                    \
    do {                                                                       \
        const int _k0 = (ch) * BK1;                                            \
        _Pragma("unroll")                                                      \
        for (int _i = 0; _i < 8; _i++) {                                       \
            const int _u = tid + (_i << 8);                                    \
            const int _t = _u >> 9;                                            \
            const int _rem = _u & 511;                                         \
            const int _row = _rem >> 2;                                        \
            const int _c = _rem & 3;                                           \
            const int _grow = ((_t < 2) ? bm : bn) + _row;                     \
            const void* _g = srcs[_t] + (size_t)_grow * H + _k0 + _c * 8;      \
            const uint32_t _sa = sb + (stage) * STAGE_B + _t * TILE_B          \
                + _row * 64 + (((_c) ^ ((_row >> 1) & 3)) << 4);               \
            asm volatile("cp.async.cg.shared.global [%0], [%1], 16;"           \
                :: "r"(_sa), "l"(_g));                                         \
        }                                                                      \
        asm volatile("cp.async.commit_group;" ::: "memory");                   \
    } while (0)

    G1_ISSUE(0, 0);

    const int NCH = H / BK1;  // 32
    for (int ch = 0; ch < NCH; ++ch) {
        const int st = ch & 1;
        if (ch + 1 < NCH) {
            G1_ISSUE(ch + 1, st ^ 1);
            asm volatile("cp.async.wait_group 1;" ::: "memory");
        } else {
            asm volatile("cp.async.wait_group 0;" ::: "memory");
        }
        __syncthreads();

        const uint32_t base = sb + st * STAGE_B;
#pragma unroll
        for (int ks = 0; ks < 2; ++ks) {
            const int cb = ks * 2 + half;
            uint32_t ah[2][4], al[2][4], bh[4][4], bl[4][4];
#pragma unroll
            for (int mt = 0; mt < 2; ++mt) {
                const int row = wm * 32 + mt * 16 + arow;
                const uint32_t off = row * 64 + ((cb ^ ((row >> 1) & 3)) << 4);
                LDSM4(ah[mt], base + 0 * TILE_B + off);
                LDSM4(al[mt], base + 1 * TILE_B + off);
            }
#pragma unroll
            for (int np = 0; np < 4; ++np) {
                const int row = wn * 64 + np * 16 + arow;
                const uint32_t off = row * 64 + ((cb ^ ((row >> 1) & 3)) << 4);
                LDSM4(bh[np], base + 2 * TILE_B + off);
                LDSM4(bl[np], base + 3 * TILE_B + off);
            }
#pragma unroll
            for (int np = 0; np < 4; ++np)
#pragma unroll
                for (int mt = 0; mt < 2; ++mt) {
                    MMA_BF16(acc[mt][2 * np],     ah[mt], bh[np][0], bh[np][2]);
                    MMA_BF16(acc[mt][2 * np + 1], ah[mt], bh[np][1], bh[np][3]);
                }
#pragma unroll
            for (int np = 0; np < 4; ++np)
#pragma unroll
                for (int mt = 0; mt < 2; ++mt) {
                    MMA_BF16(acc[mt][2 * np],     al[mt], bh[np][0], bh[np][2]);
                    MMA_BF16(acc[mt][2 * np + 1], al[mt], bh[np][1], bh[np][3]);
                }
#pragma unroll
            for (int np = 0; np < 4; ++np)
#pragma unroll
                for (int mt = 0; mt < 2; ++mt) {
                    MMA_BF16(acc[mt][2 * np],     ah[mt], bl[np][0], bl[np][2]);
                    MMA_BF16(acc[mt][2 * np + 1], ah[mt], bl[np][1], bl[np][3]);
                }
        }
        __syncthreads();
    }

    // Epilogue: tanh(D + bias[h]) split to bf16 hi/lo, stored [b][s][h].
    const int b_ = bm / S;
    const int s_base = (bm % S) + wm * 32 + (lane >> 2);
    const int n_base = bn + wn * 64;
#pragma unroll
    for (int mt = 0; mt < 2; ++mt) {
        const int s0 = s_base + mt * 16;
#pragma unroll
        for (int nt = 0; nt < 8; ++nt) {
            const int n0 = n_base + nt * 8 + 2 * (lane & 3);
            const float bv0 = bias[n0];
            const float bv1 = bias[n0 + 1];
            const size_t r0 = ((size_t)b_ * S + s0) * H + n0;
            const size_t r1 = ((size_t)b_ * S + s0 + 8) * H + n0;
            split_store2(&g_Ench[r0], &g_Encl[r0],
                         tanhf(acc[mt][nt][0] + bv0), tanhf(acc[mt][nt][1] + bv1));
            split_store2(&g_Ench[r1], &g_Encl[r1],
                         tanhf(acc[mt][nt][2] + bv0), tanhf(acc[mt][nt][3] + bv1));
        }
    }
}

// ---------------------------------------------------------------------------
// GEMM2: scores = dec.enc + ib; CTA 32(t)x64(s), BK=32, 4 warps = 2x2,
// warp tile 16x32, grid (8,8,4)=256 CTAs.
// NOW 3-STAGE cp.async pipeline (2 chunks of lookahead) to cover the
// DRAM/L2 latency that left ~9us exposed at 2 stages.
// Stage 12 KB: [Ah 2K, Al 2K, Bh 4K, Bl 4K], 3 stages = 36 KB static.
// ---------------------------------------------------------------------------
#define G2_TA 2048                 // 32 rows x 64 B
#define G2_TB 4096                 // 64 rows x 64 B
#define G2STAGE (2 * G2_TA + 2 * G2_TB)   // 12 KB

__global__ __launch_bounds__(128, 3) void gemm2_mma(const float* __restrict__ ib)
{
    __shared__ __align__(128) char smem[3 * G2STAGE];   // 36 KB
    const uint32_t sb = smem_to_u32(smem);
    const int tid = threadIdx.x;
    const int lane = tid & 31;
    const int wid = tid >> 5;
    const int wm = wid & 1;           // 0..1 (t)
    const int wn = wid >> 1;          // 0..1 (s)
    const int b  = blockIdx.z;
    const int bt = blockIdx.y * 32;
    const int bs = blockIdx.x * 64;

    const unsigned short* srcA[2] = {
        g_Dech + (size_t)b * T * H, g_Decl + (size_t)b * T * H};
    const unsigned short* srcB[2] = {
        g_Ench + (size_t)b * S * H, g_Encl + (size_t)b * S * H};

    float acc[4][4];
#pragma unroll
    for (int nt = 0; nt < 4; nt++)
#pragma unroll
        for (int q = 0; q < 4; q++) acc[nt][q] = 0.f;

    const int arow = lane & 15;
    const int half = lane >> 4;

    // 768 16B-units/stage: [0,128)=Ah, [128,256)=Al, [256,512)=Bh, [512,768)=Bl
#define G2_ISSUE(ch, stage)                                                    \
    do {                                                                       \
        const int _k0 = (ch) * BK1;                                            \
        _Pragma("unroll")                                                      \
        for (int _i = 0; _i < 6; _i++) {                                       \
            const int _u = tid + (_i << 7);                                    \
            const unsigned short* _src;                                        \
            uint32_t _tb; int _rr, _gr;                                        \
            if (_u < 256) {                                                    \
                _src = srcA[_u >> 7];                                          \
                _tb = (_u < 128) ? 0u : (uint32_t)G2_TA;                       \
                _rr = (_u & 127) >> 2;                                         \
                _gr = bt + _rr;                                                \
            } else {                                                           \
                _src = srcB[(_u - 256) >> 8];                                  \
                _tb = (_u < 512) ? (uint32_t)(2 * G2_TA)                       \
                                 : (uint32_t)(2 * G2_TA + G2_TB);              \
                _rr = (_u & 255) >> 2;                                         \
                _gr = bs + _rr;                                                \
            }                                                                  \
            const int _c = _u & 3;                                             \
            const void* _g = _src + (size_t)_gr * H + _k0 + _c * 8;            \
            const uint32_t _sa = sb + (stage) * G2STAGE + _tb                  \
                + _rr * 64 + (((_c) ^ ((_rr >> 1) & 3)) << 4);                 \
            asm volatile("cp.async.cg.shared.global [%0], [%1], 16;"           \
                :: "r"(_sa), "l"(_g));                                         \
        }                                                                      \
        asm volatile("cp.async.commit_group;" ::: "memory");                   \
    } while (0)

    G2_ISSUE(0, 0);
    G2_ISSUE(1, 1);

    const int NCH = H / BK1;   // 32
    for (int ch = 0; ch < NCH; ++ch) {
        // Issue-ahead into slot (ch+2)%3 (last consumed at iter ch-1, whose
        // trailing __syncthreads guards the reuse), then drain to stage ch.
        if (ch + 2 < NCH) {
            const int slot = (ch + 2) % 3;
            G2_ISSUE(ch + 2, slot);
            asm volatile("cp.async.wait_group 2;" ::: "memory");
        } else if (ch + 1 < NCH) {
            asm volatile("cp.async.wait_group 1;" ::: "memory");
        } else {
            asm volatile("cp.async.wait_group 0;" ::: "memory");
        }
        __syncthreads();

        const uint32_t base = sb + (ch % 3) * G2STAGE;
#pragma unroll
        for (int ks = 0; ks < 2; ++ks) {
            const int cb = ks * 2 + half;
            uint32_t ah[4], al[4], bh[2][4], bl[2][4];
            {
                const int row = wm * 16 + arow;
                const uint32_t off = row * 64 + ((cb ^ ((row >> 1) & 3)) << 4);
                LDSM4(ah, base + off);
                LDSM4(al, base + G2_TA + off);
            }
#pragma unroll
            for (int np = 0; np < 2; ++np) {
                const int row = wn * 32 + np * 16 + arow;
                const uint32_t off = row * 64 + ((cb ^ ((row >> 1) & 3)) << 4);
                LDSM4(bh[np], base + 2 * G2_TA + off);
                LDSM4(bl[np], base + 2 * G2_TA + G2_TB + off);
            }
#pragma unroll
            for (int np = 0; np < 2; ++np) {
                MMA_BF16(acc[2 * np],     ah, bh[np][0], bh[np][2]);
                MMA_BF16(acc[2 * np + 1], ah, bh[np][1], bh[np][3]);
            }
#pragma unroll
            for (int np = 0; np < 2; ++np) {
                MMA_BF16(acc[2 * np],     al, bh[np][0], bh[np][2]);
                MMA_BF16(acc[2 * np + 1], al, bh[np][1], bh[np][3]);
            }
#pragma unroll
            for (int np = 0; np < 2; ++np) {
                MMA_BF16(acc[2 * np],     ah, bl[np][0], bl[np][2]);
                MMA_BF16(acc[2 * np + 1], ah, bl[np][1], bl[np][3]);
            }
        }
        __syncthreads();
    }

    // Epilogue: + input_bias, fp32 scores.
    const int t0 = bt + wm * 16 + (lane >> 2);
    const int s_col = bs + wn * 32;
#pragma unroll
    for (int nt = 0; nt < 4; ++nt) {
        const int s = s_col + nt * 8 + 2 * (lane & 3);
        const float b0 = ib[b * S + s];
        const float b1 = ib[b * S + s + 1];
        float2 v0 = make_float2(acc[nt][0] + b0, acc[nt][1] + b1);
        float2 v1 = make_float2(acc[nt][2] + b0, acc[nt][3] + b1);
        *(float2*)&g_scores[((size_t)b * T + t0) * S + s] = v0;
        *(float2*)&g_scores[((size_t)b * T + t0 + 8) * S + s] = v1;
    }
}

// ---------------------------------------------------------------------------
// Kernel 3: 512 threads — zero vocab slice, softmax over S (1 elt/thread),
// scatter-add.
// ---------------------------------------------------------------------------
__global__ __launch_bounds__(512) void softmax_scatter(
    const int* __restrict__ ids, float* __restrict__ out)
{
    const int bt = blockIdx.x;
    const int b = bt / T;
    const int tid = threadIdx.x;

    const float* row = &g_scores[(size_t)bt * S];
    float* orow = out + (size_t)bt * V;

    const float4 z = make_float4(0.f, 0.f, 0.f, 0.f);
    float4* orow4 = (float4*)orow;
#pragma unroll 4
    for (int i = tid; i < V / 4; i += 512) orow4[i] = z;

    __shared__ float red[16];

    float v = row[tid];

    float m = v;
#pragma unroll
    for (int o = 16; o > 0; o >>= 1)
        m = fmaxf(m, __shfl_xor_sync(0xFFFFFFFFu, m, o));
    if ((tid & 31) == 0) red[tid >> 5] = m;
    __syncthreads();
    if (tid < 16) {
        float t = red[tid];
#pragma unroll
        for (int o = 8; o > 0; o >>= 1)
            t = fmaxf(t, __shfl_xor_sync(0xFFFFu, t, o));
        red[tid] = t;
    }
    __syncthreads();
    const float mx = red[0];

    float e = expf(v - mx);
    float s = e;
#pragma unroll
    for (int o = 16; o > 0; o >>= 1)
        s += __shfl_xor_sync(0xFFFFFFFFu, s, o);
    __syncthreads();
    if ((tid & 31) == 0) red[tid >> 5] = s;
    __syncthreads();
    if (tid < 16) {
        float t = red[tid];
#pragma unroll
        for (int o = 8; o > 0; o >>= 1)
            t += __shfl_xor_sync(0xFFFFu, t, o);
        red[tid] = t;
    }
    __syncthreads();
    const float inv = 1.0f / red[0];

    atomicAdd(&orow[ids[b * S + tid]], e * inv);
}

// ---------------------------------------------------------------------------
extern "C" void kernel_launch(void* const* d_in, const int* in_sizes, int n_in,
                              void* d_out, int out_size)
{
    const int*   inputs = (const int*)d_in[0];    // [B,S] int32
    const float* E      = (const float*)d_in[1];  // [B,S,H]
    const float* Dec    = (const float*)d_in[2];  // [B,T,H]
    const float* ib     = (const float*)d_in[3];  // [B,S]
    const float* Wp     = (const float*)d_in[4];  // [H,H]
    const float* bp     = (const float*)d_in[5];  // [H]
    float* out = (float*)d_out;                   // [B,T,V]

    static bool attr_set = false;
    if (!attr_set) {
        cudaFuncSetAttribute(gemm1_mma,
                             cudaFuncAttributeMaxDynamicSharedMemorySize, SMEM_G1);
        attr_set = true;
    }

    convert_splits<<<(E_F4 + D_F4) / 256, 256>>>(E, Dec);
    convert_W<<<dim3(H / 32, H / 32), 256>>>(Wp);

    dim3 g1(H / 128, M1 / 128);                   // (8, 16) = 128 CTAs
    gemm1_mma<<<g1, 256, SMEM_G1>>>(bp);

    dim3 g2(S / 64, T / 32, B);                   // (8, 8, 4) = 256 CTAs
    gemm2_mma<<<g2, 128>>>(ib);

    softmax_scatter<<<B * T, 512>>>(inputs, out);
}

// round 14
// speedup vs baseline: 1.0445x; 1.0445x over previous
#include <cuda_runtime.h>
#include <cuda_bf16.h>
#include <math.h>
#include <cstdint>

// Problem constants (fixed shapes)
#define B 4
#define S 512
#define T 256
#define H 1024
#define V 32000
#define M1 (B * S)   // 2048

// Scratch (device globals — no allocations allowed)
__device__ float g_scores[B * T * S];        // [b][t][s], 2 MB
__device__ unsigned short g_Eh[M1 * H];      // bf16 hi of E   [M,K]
__device__ unsigned short g_El[M1 * H];      // bf16 lo of E   [M,K]
__device__ unsigned short g_Wh[H * H];       // bf16 hi of W^T [N,K]
__device__ unsigned short g_Wl[H * H];       // bf16 lo of W^T [N,K]
__device__ unsigned short g_Ench[B * S * H]; // bf16 hi of enc [b][s][h]
__device__ unsigned short g_Encl[B * S * H]; // bf16 lo of enc [b][s][h]
__device__ unsigned short g_Dech[B * T * H]; // bf16 hi of dec [b][t][h]
__device__ unsigned short g_Decl[B * T * H]; // bf16 lo of dec [b][t][h]

// ---------------------------------------------------------------------------
// Arch-generic tensor-core primitives (legal on plain sm_103 target)
// ---------------------------------------------------------------------------
#define LDSM4(r, a)                                                            \
    asm volatile("ldmatrix.sync.aligned.m8n8.x4.shared.b16 {%0,%1,%2,%3}, [%4];" \
        : "=r"((r)[0]), "=r"((r)[1]), "=r"((r)[2]), "=r"((r)[3]) : "r"(a))

#define MMA_BF16(d, a, b0, b1)                                                 \
    asm volatile(                                                              \
        "mma.sync.aligned.m16n8k16.row.col.f32.bf16.bf16.f32 "                 \
        "{%0,%1,%2,%3}, {%4,%5,%6,%7}, {%8,%9}, {%0,%1,%2,%3};"                \
        : "+f"((d)[0]), "+f"((d)[1]), "+f"((d)[2]), "+f"((d)[3])               \
        : "r"((a)[0]), "r"((a)[1]), "r"((a)[2]), "r"((a)[3]),                  \
          "r"(b0), "r"(b1))

__device__ __forceinline__ uint32_t smem_to_u32(const void* p) {
    uint32_t a;
    asm("{ .reg .u64 t; cvta.to.shared.u64 t, %1; cvt.u32.u64 %0, t; }"
        : "=r"(a) : "l"(p));
    return a;
}

__device__ __forceinline__ void split_store2(
    unsigned short* hp, unsigned short* lp, float v0, float v1)
{
    __nv_bfloat16 h0 = __float2bfloat16_rn(v0);
    __nv_bfloat16 h1 = __float2bfloat16_rn(v1);
    unsigned short l0 = __bfloat16_as_ushort(__float2bfloat16_rn(v0 - __bfloat162float(h0)));
    unsigned short l1 = __bfloat16_as_ushort(__float2bfloat16_rn(v1 - __bfloat162float(h1)));
    *(uint32_t*)hp = (uint32_t)__bfloat16_as_ushort(h0) |
                     ((uint32_t)__bfloat16_as_ushort(h1) << 16);
    *(uint32_t*)lp = (uint32_t)l0 | ((uint32_t)l1 << 16);
}

// ---------------------------------------------------------------------------
// Converter: E and Dec fp32 -> bf16 hi/lo in ONE kernel.
// ---------------------------------------------------------------------------
#define E_F4 (M1 * H / 4)          // 524288
#define D_F4 (B * T * H / 4)       // 262144

__global__ __launch_bounds__(256) void convert_splits(
    const float* __restrict__ E, const float* __restrict__ Dec)
{
    const int idx = blockIdx.x * 256 + threadIdx.x;
    const float* src;
    unsigned short *hi, *lo;
    int j;
    if (idx < E_F4) {
        src = E; hi = g_Eh; lo = g_El; j = idx;
    } else {
        src = Dec; hi = g_Dech; lo = g_Decl; j = idx - E_F4;
    }
    const float4 v = ((const float4*)src)[j];
    ushort4 h, l;
    const float* vf = (const float*)&v;
    unsigned short* hp = (unsigned short*)&h;
    unsigned short* lp = (unsigned short*)&l;
#pragma unroll
    for (int i = 0; i < 4; i++) {
        __nv_bfloat16 hb = __float2bfloat16_rn(vf[i]);
        hp[i] = __bfloat16_as_ushort(hb);
        lp[i] = __bfloat16_as_ushort(__float2bfloat16_rn(vf[i] - __bfloat162float(hb)));
    }
    ((ushort4*)hi)[j] = h;
    ((ushort4*)lo)[j] = l;
}

__global__ __launch_bounds__(256) void convert_W(const float* __restrict__ W)
{
    __shared__ float t[32][33];
    const int k0 = blockIdx.x * 32;
    const int n0 = blockIdx.y * 32;
    const int tx = threadIdx.x & 31;
    const int ty = threadIdx.x >> 5;
#pragma unroll
    for (int r = 0; r < 4; r++) {
        const int k = ty + r * 8;
        t[k][tx] = W[(size_t)(k0 + k) * H + n0 + tx];
    }
    __syncthreads();
#pragma unroll
    for (int r = 0; r < 4; r++) {
        const int n = ty + r * 8;
        const float x = t[tx][n];
        __nv_bfloat16 hb = __float2bfloat16_rn(x);
        g_Wh[(size_t)(n0 + n) * H + k0 + tx] = __bfloat16_as_ushort(hb);
        g_Wl[(size_t)(n0 + n) * H + k0 + tx] =
            __bfloat16_as_ushort(__float2bfloat16_rn(x - __bfloat162float(hb)));
    }
}

// ---------------------------------------------------------------------------
// GEMM1 (R10/R12 config — 48.7us, established floor for this path):
// CTA 128x128, BK=32, 2-stage cp.async, 64 KB dyn smem,
// 8 warps = 4(M) x 2(N), warp 32x64, hi/lo 3-pass.
// ---------------------------------------------------------------------------
#define BK1 32
#define TILE_B (128 * 64)         // 8 KB per tile
#define STAGE_B (4 * TILE_B)      // Ah, Al, Bh, Bl = 32 KB
#define SMEM_G1 (2 * STAGE_B)     // 64 KB

__global__ __launch_bounds__(256, 1) void gemm1_mma(const float* __restrict__ bias)
{
    extern __shared__ __align__(128) char smem[];
    const uint32_t sb = smem_to_u32(smem);
    const int tid = threadIdx.x;
    const int lane = tid & 31;
    const int wid = tid >> 5;
    const int wm = wid & 3;           // 0..3 (M)
    const int wn = wid >> 2;          // 0..1 (N)
    const int bm = blockIdx.y * 128;  // (b,s) tile
    const int bn = blockIdx.x * 128;  // h tile

    const unsigned short* srcs[4] = {g_Eh, g_El, g_Wh, g_Wl};

    float acc[2][8][4];
#pragma unroll
    for (int mt = 0; mt < 2; mt++)
#pragma unroll
        for (int nt = 0; nt < 8; nt++)
#pragma unroll
            for (int q = 0; q < 4; q++) acc[mt][nt][q] = 0.f;

    const int arow = lane & 15;
    const int half = lane >> 4;

#define G1_ISSUE(ch, stage)                                                    \
    do {                                                                       \
        const int _k0 = (ch) * BK1;                                            \
        _Pragma("unroll")                                                      \
        for (int _i = 0; _i < 8; _i++) {                                       \
            const int _u = tid + (_i << 8);                                    \
            const int _t = _u >> 9;                                            \
            const int _rem = _u & 511;                                         \
            const int _row = _rem >> 2;                                        \
            const int _c = _rem & 3;                                           \
            const int _grow = ((_t < 2) ? bm : bn) + _row;                     \
            const void* _g = srcs[_t] + (size_t)_grow * H + _k0 + _c * 8;      \
            const uint32_t _sa = sb + (stage) * STAGE_B + _t * TILE_B          \
                + _row * 64 + (((_c) ^ ((_row >> 1) & 3)) << 4);               \
            asm volatile("cp.async.cg.shared.global [%0], [%1], 16;"           \
                :: "r"(_sa), "l"(_g));                                         \
        }                                                                      \
        asm volatile("cp.async.commit_group;" ::: "memory");                   \
    } while (0)

    G1_ISSUE(0, 0);

    const int NCH = H / BK1;  // 32
    for (int ch = 0; ch < NCH; ++ch) {
        const int st = ch & 1;
        if (ch + 1 < NCH) {
            G1_ISSUE(ch + 1, st ^ 1);
            asm volatile("cp.async.wait_group 1;" ::: "memory");
        } else {
            asm volatile("cp.async.wait_group 0;" ::: "memory");
        }
        __syncthreads();

        const uint32_t base = sb + st * STAGE_B;
#pragma unroll
        for (int ks = 0; ks < 2; ++ks) {
            const int cb = ks * 2 + half;
            uint32_t ah[2][4], al[2][4], bh[4][4], bl[4][4];
#pragma unroll
            for (int mt = 0; mt < 2; ++mt) {
                const int row = wm * 32 + mt * 16 + arow;
                const uint32_t off = row * 64 + ((cb ^ ((row >> 1) & 3)) << 4);
                LDSM4(ah[mt], base + 0 * TILE_B + off);
                LDSM4(al[mt], base + 1 * TILE_B + off);
            }
#pragma unroll
            for (int np = 0; np < 4; ++np) {
                const int row = wn * 64 + np * 16 + arow;
                const uint32_t off = row * 64 + ((cb ^ ((row >> 1) & 3)) << 4);
                LDSM4(bh[np], base + 2 * TILE_B + off);
                LDSM4(bl[np], base + 3 * TILE_B + off);
            }
#pragma unroll
            for (int np = 0; np < 4; ++np)
#pragma unroll
                for (int mt = 0; mt < 2; ++mt) {
                    MMA_BF16(acc[mt][2 * np],     ah[mt], bh[np][0], bh[np][2]);
                    MMA_BF16(acc[mt][2 * np + 1], ah[mt], bh[np][1], bh[np][3]);
                }
#pragma unroll
            for (int np = 0; np < 4; ++np)
#pragma unroll
                for (int mt = 0; mt < 2; ++mt) {
                    MMA_BF16(acc[mt][2 * np],     al[mt], bh[np][0], bh[np][2]);
                    MMA_BF16(acc[mt][2 * np + 1], al[mt], bh[np][1], bh[np][3]);
                }
#pragma unroll
            for (int np = 0; np < 4; ++np)
#pragma unroll
                for (int mt = 0; mt < 2; ++mt) {
                    MMA_BF16(acc[mt][2 * np],     ah[mt], bl[np][0], bl[np][2]);
                    MMA_BF16(acc[mt][2 * np + 1], ah[mt], bl[np][1], bl[np][3]);
                }
        }
        __syncthreads();
    }

    // Epilogue: tanh(D + bias[h]) split to bf16 hi/lo, stored [b][s][h].
    const int b_ = bm / S;
    const int s_base = (bm % S) + wm * 32 + (lane >> 2);
    const int n_base = bn + wn * 64;
#pragma unroll
    for (int mt = 0; mt < 2; ++mt) {
        const int s0 = s_base + mt * 16;
#pragma unroll
        for (int nt = 0; nt < 8; ++nt) {
            const int n0 = n_base + nt * 8 + 2 * (lane & 3);
            const float bv0 = bias[n0];
            const float bv1 = bias[n0 + 1];
            const size_t r0 = ((size_t)b_ * S + s0) * H + n0;
            const size_t r1 = ((size_t)b_ * S + s0 + 8) * H + n0;
            split_store2(&g_Ench[r0], &g_Encl[r0],
                         tanhf(acc[mt][nt][0] + bv0), tanhf(acc[mt][nt][1] + bv1));
            split_store2(&g_Ench[r1], &g_Encl[r1],
                         tanhf(acc[mt][nt][2] + bv0), tanhf(acc[mt][nt][3] + bv1));
        }
    }
}

// ---------------------------------------------------------------------------
// GEMM2: scores = dec.enc + ib; CTA 32(t)x64(s), BK=64 (halved barrier
// cadence vs R12), 2-stage cp.async, 4 warps = 2x2, warp tile 16x32.
// Grid (8,8,4)=256 CTAs. Stage 24 KB (128-B rows): [Ah 4K, Al 4K,
// Bh 8K, Bl 8K], 2 stages = 48 KB static. Swizzle c^(row&7) on 16B cols.
// ---------------------------------------------------------------------------
#define BK2 64
#define G2_TA 4096                 // 32 rows x 128 B
#define G2_TB 8192                 // 64 rows x 128 B
#define G2STAGE (2 * G2_TA + 2 * G2_TB)   // 24 KB

__global__ __launch_bounds__(128, 2) void gemm2_mma(const float* __restrict__ ib)
{
    __shared__ __align__(128) char smem[2 * G2STAGE];   // 48 KB
    const uint32_t sb = smem_to_u32(smem);
    const int tid = threadIdx.x;
    const int lane = tid & 31;
    const int wid = tid >> 5;
    const int wm = wid & 1;           // 0..1 (t)
    const int wn = wid >> 1;          // 0..1 (s)
    const int b  = blockIdx.z;
    const int bt = blockIdx.y * 32;
    const int bs = blockIdx.x * 64;

    const unsigned short* srcA[2] = {
        g_Dech + (size_t)b * T * H, g_Decl + (size_t)b * T * H};
    const unsigned short* srcB[2] = {
        g_Ench + (size_t)b * S * H, g_Encl + (size_t)b * S * H};

    float acc[4][4];
#pragma unroll
    for (int nt = 0; nt < 4; nt++)
#pragma unroll
        for (int q = 0; q < 4; q++) acc[nt][q] = 0.f;

    const int arow = lane & 15;
    const int half = lane >> 4;

    // 1536 16B-units/stage: [0,256)=Ah, [256,512)=Al, [512,1024)=Bh, [1024,1536)=Bl
    // Rows are 128 B = 8 units; c in 0..7; swizzle c ^= (row & 7).
#define G2_ISSUE(ch, stage)                                                    \
    do {                                                                       \
        const int _k0 = (ch) * BK2;                                            \
        _Pragma("unroll")                                                      \
        for (int _i = 0; _i < 12; _i++) {                                      \
            const int _u = tid + (_i << 7);                                    \
            const unsigned short* _src;                                        \
            uint32_t _tb; int _rr, _gr;                                        \
            if (_u < 512) {                                                    \
                _src = srcA[_u >> 8];                                          \
                _tb = (_u < 256) ? 0u : (uint32_t)G2_TA;                       \
                _rr = (_u & 255) >> 3;                                         \
                _gr = bt + _rr;                                                \
            } else {                                                           \
                _src = srcB[(_u - 512) >> 9];                                  \
                _tb = (_u < 1024) ? (uint32_t)(2 * G2_TA)                      \
                                  : (uint32_t)(2 * G2_TA + G2_TB);             \
                _rr = (_u & 511) >> 3;                                         \
                _gr = bs + _rr;                                                \
            }                                                                  \
            const int _c = _u & 7;                                             \
            const void* _g = _src + (size_t)_gr * H + _k0 + _c * 8;            \
            const uint32_t _sa = sb + (stage) * G2STAGE + _tb                  \
                + _rr * 128 + (((_c) ^ (_rr & 7)) << 4);                       \
            asm volatile("cp.async.cg.shared.global [%0], [%1], 16;"           \
                :: "r"(_sa), "l"(_g));                                         \
        }                                                                      \
        asm volatile("cp.async.commit_group;" ::: "memory");                   \
    } while (0)

    G2_ISSUE(0, 0);

    const int NCH = H / BK2;   // 16
    for (int ch = 0; ch < NCH; ++ch) {
        const int st = ch & 1;
        if (ch + 1 < NCH) {
            G2_ISSUE(ch + 1, st ^ 1);
            asm volatile("cp.async.wait_group 1;" ::: "memory");
        } else {
            asm volatile("cp.async.wait_group 0;" ::: "memory");
        }
        __syncthreads();

        const uint32_t base = sb + st * G2STAGE;
#pragma unroll
        for (int ks = 0; ks < 4; ++ks) {           // four k16 per BK=64
            const int cb = ks * 2 + half;          // 0..7
            uint32_t ah[4], al[4], bh[2][4], bl[2][4];
            {
                const int row = wm * 16 + arow;
                const uint32_t off = row * 128 + ((cb ^ (row & 7)) << 4);
                LDSM4(ah, base + off);
                LDSM4(al, base + G2_TA + off);
            }
#pragma unroll
            for (int np = 0; np < 2; ++np) {
                const int row = wn * 32 + np * 16 + arow;
                const uint32_t off = row * 128 + ((cb ^ (row & 7)) << 4);
                LDSM4(bh[np], base + 2 * G2_TA + off);
                LDSM4(bl[np], base + 2 * G2_TA + G2_TB + off);
            }
#pragma unroll
            for (int np = 0; np < 2; ++np) {
                MMA_BF16(acc[2 * np],     ah, bh[np][0], bh[np][2]);
                MMA_BF16(acc[2 * np + 1], ah, bh[np][1], bh[np][3]);
            }
#pragma unroll
            for (int np = 0; np < 2; ++np) {
                MMA_BF16(acc[2 * np],     al, bh[np][0], bh[np][2]);
                MMA_BF16(acc[2 * np + 1], al, bh[np][1], bh[np][3]);
            }
#pragma unroll
            for (int np = 0; np < 2; ++np) {
                MMA_BF16(acc[2 * np],     ah, bl[np][0], bl[np][2]);
                MMA_BF16(acc[2 * np + 1], ah, bl[np][1], bl[np][3]);
            }
        }
        __syncthreads();
    }

    // Epilogue: + input_bias, fp32 scores.
    const int t0 = bt + wm * 16 + (lane >> 2);
    const int s_col = bs + wn * 32;
#pragma unroll
    for (int nt = 0; nt < 4; ++nt) {
        const int s = s_col + nt * 8 + 2 * (lane & 3);
        const float b0 = ib[b * S + s];
        const float b1 = ib[b * S + s + 1];
        float2 v0 = make_float2(acc[nt][0] + b0, acc[nt][1] + b1);
        float2 v1 = make_float2(acc[nt][2] + b0, acc[nt][3] + b1);
        *(float2*)&g_scores[((size_t)b * T + t0) * S + s] = v0;
        *(float2*)&g_scores[((size_t)b * T + t0 + 8) * S + s] = v1;
    }
}

// ---------------------------------------------------------------------------
// Kernel 3: 512 threads — zero vocab slice, softmax over S (1 elt/thread),
// scatter-add.
// ---------------------------------------------------------------------------
__global__ __launch_bounds__(512) void softmax_scatter(
    const int* __restrict__ ids, float* __restrict__ out)
{
    const int bt = blockIdx.x;
    const int b = bt / T;
    const int tid = threadIdx.x;

    const float* row = &g_scores[(size_t)bt * S];
    float* orow = out + (size_t)bt * V;

    const float4 z = make_float4(0.f, 0.f, 0.f, 0.f);
    float4* orow4 = (float4*)orow;
#pragma unroll 4
    for (int i = tid; i < V / 4; i += 512) orow4[i] = z;

    __shared__ float red[16];

    float v = row[tid];

    float m = v;
#pragma unroll
    for (int o = 16; o > 0; o >>= 1)
        m = fmaxf(m, __shfl_xor_sync(0xFFFFFFFFu, m, o));
    if ((tid & 31) == 0) red[tid >> 5] = m;
    __syncthreads();
    if (tid < 16) {
        float t = red[tid];
#pragma unroll
        for (int o = 8; o > 0; o >>= 1)
            t = fmaxf(t, __shfl_xor_sync(0xFFFFu, t, o));
        red[tid] = t;
    }
    __syncthreads();
    const float mx = red[0];

    float e = expf(v - mx);
    float s = e;
#pragma unroll
    for (int o = 16; o > 0; o >>= 1)
        s += __shfl_xor_sync(0xFFFFFFFFu, s, o);
    __syncthreads();
    if ((tid & 31) == 0) red[tid >> 5] = s;
    __syncthreads();
    if (tid < 16) {
        float t = red[tid];
#pragma unroll
        for (int o = 8; o > 0; o >>= 1)
            t += __shfl_xor_sync(0xFFFFu, t, o);
        red[tid] = t;
    }
    __syncthreads();
    const float inv = 1.0f / red[0];

    atomicAdd(&orow[ids[b * S + tid]], e * inv);
}

// ---------------------------------------------------------------------------
extern "C" void kernel_launch(void* const* d_in, const int* in_sizes, int n_in,
                              void* d_out, int out_size)
{
    const int*   inputs = (const int*)d_in[0];    // [B,S] int32
    const float* E      = (const float*)d_in[1];  // [B,S,H]
    const float* Dec    = (const float*)d_in[2];  // [B,T,H]
    const float* ib     = (const float*)d_in[3];  // [B,S]
    const float* Wp     = (const float*)d_in[4];  // [H,H]
    const float* bp     = (const float*)d_in[5];  // [H]
    float* out = (float*)d_out;                   // [B,T,V]

    static bool attr_set = false;
    if (!attr_set) {
        cudaFuncSetAttribute(gemm1_mma,
                             cudaFuncAttributeMaxDynamicSharedMemorySize, SMEM_G1);
        attr_set = true;
    }

    convert_splits<<<(E_F4 + D_F4) / 256, 256>>>(E, Dec);
    convert_W<<<dim3(H / 32, H / 32), 256>>>(Wp);

    dim3 g1(H / 128, M1 / 128);                   // (8, 16) = 128 CTAs
    gemm1_mma<<<g1, 256, SMEM_G1>>>(bp);

    dim3 g2(S / 64, T / 32, B);                   // (8, 8, 4) = 256 CTAs
    gemm2_mma<<<g2, 128>>>(ib);

    softmax_scatter<<<B * T, 512>>>(inputs, out);
}

// round 15
// speedup vs baseline: 1.0693x; 1.0238x over previous
#include <cuda_runtime.h>
#include <cuda_bf16.h>
#include <math.h>
#include <cstdint>

// Problem constants (fixed shapes)
#define B 4
#define S 512
#define T 256
#define H 1024
#define V 32000
#define M1 (B * S)   // 2048

// Scratch (device globals — no allocations allowed)
__device__ float g_scores[B * T * S];        // [b][t][s], 2 MB
__device__ unsigned short g_Eh[M1 * H];      // bf16 hi of E   [M,K]
__device__ unsigned short g_El[M1 * H];      // bf16 lo of E   [M,K]
__device__ unsigned short g_Wh[H * H];       // bf16 hi of W^T [N,K]
__device__ unsigned short g_Wl[H * H];       // bf16 lo of W^T [N,K]
__device__ unsigned short g_Ench[B * S * H]; // bf16 hi of enc [b][s][h]
__device__ unsigned short g_Encl[B * S * H]; // bf16 lo of enc [b][s][h]
__device__ unsigned short g_Dech[B * T * H]; // bf16 hi of dec [b][t][h]
__device__ unsigned short g_Decl[B * T * H]; // bf16 lo of dec [b][t][h]

// ---------------------------------------------------------------------------
// Arch-generic tensor-core primitives (legal on plain sm_103 target)
// ---------------------------------------------------------------------------
#define LDSM4(r, a)                                                            \
    asm volatile("ldmatrix.sync.aligned.m8n8.x4.shared.b16 {%0,%1,%2,%3}, [%4];" \
        : "=r"((r)[0]), "=r"((r)[1]), "=r"((r)[2]), "=r"((r)[3]) : "r"(a))

#define MMA_BF16(d, a, b0, b1)                                                 \
    asm volatile(                                                              \
        "mma.sync.aligned.m16n8k16.row.col.f32.bf16.bf16.f32 "                 \
        "{%0,%1,%2,%3}, {%4,%5,%6,%7}, {%8,%9}, {%0,%1,%2,%3};"                \
        : "+f"((d)[0]), "+f"((d)[1]), "+f"((d)[2]), "+f"((d)[3])               \
        : "r"((a)[0]), "r"((a)[1]), "r"((a)[2]), "r"((a)[3]),                  \
          "r"(b0), "r"(b1))

__device__ __forceinline__ uint32_t smem_to_u32(const void* p) {
    uint32_t a;
    asm("{ .reg .u64 t; cvta.to.shared.u64 t, %1; cvt.u32.u64 %0, t; }"
        : "=r"(a) : "l"(p));
    return a;
}

__device__ __forceinline__ void split_store2(
    unsigned short* hp, unsigned short* lp, float v0, float v1)
{
    __nv_bfloat16 h0 = __float2bfloat16_rn(v0);
    __nv_bfloat16 h1 = __float2bfloat16_rn(v1);
    unsigned short l0 = __bfloat16_as_ushort(__float2bfloat16_rn(v0 - __bfloat162float(h0)));
    unsigned short l1 = __bfloat16_as_ushort(__float2bfloat16_rn(v1 - __bfloat162float(h1)));
    *(uint32_t*)hp = (uint32_t)__bfloat16_as_ushort(h0) |
                     ((uint32_t)__bfloat16_as_ushort(h1) << 16);
    *(uint32_t*)lp = (uint32_t)l0 | ((uint32_t)l1 << 16);
}

// ---------------------------------------------------------------------------
// Converter: E and Dec fp32 -> bf16 hi/lo in ONE kernel.
// ---------------------------------------------------------------------------
#define E_F4 (M1 * H / 4)          // 524288
#define D_F4 (B * T * H / 4)       // 262144

__global__ __launch_bounds__(256) void convert_splits(
    const float* __restrict__ E, const float* __restrict__ Dec)
{
    const int idx = blockIdx.x * 256 + threadIdx.x;
    const float* src;
    unsigned short *hi, *lo;
    int j;
    if (idx < E_F4) {
        src = E; hi = g_Eh; lo = g_El; j = idx;
    } else {
        src = Dec; hi = g_Dech; lo = g_Decl; j = idx - E_F4;
    }
    const float4 v = ((const float4*)src)[j];
    ushort4 h, l;
    const float* vf = (const float*)&v;
    unsigned short* hp = (unsigned short*)&h;
    unsigned short* lp = (unsigned short*)&l;
#pragma unroll
    for (int i = 0; i < 4; i++) {
        __nv_bfloat16 hb = __float2bfloat16_rn(vf[i]);
        hp[i] = __bfloat16_as_ushort(hb);
        lp[i] = __bfloat16_as_ushort(__float2bfloat16_rn(vf[i] - __bfloat162float(hb)));
    }
    ((ushort4*)hi)[j] = h;
    ((ushort4*)lo)[j] = l;
}

__global__ __launch_bounds__(256) void convert_W(const float* __restrict__ W)
{
    __shared__ float t[32][33];
    const int k0 = blockIdx.x * 32;
    const int n0 = blockIdx.y * 32;
    const int tx = threadIdx.x & 31;
    const int ty = threadIdx.x >> 5;
#pragma unroll
    for (int r = 0; r < 4; r++) {
        const int k = ty + r * 8;
        t[k][tx] = W[(size_t)(k0 + k) * H + n0 + tx];
    }
    __syncthreads();
#pragma unroll
    for (int r = 0; r < 4; r++) {
        const int n = ty + r * 8;
        const float x = t[tx][n];
        __nv_bfloat16 hb = __float2bfloat16_rn(x);
        g_Wh[(size_t)(n0 + n) * H + k0 + tx] = __bfloat16_as_ushort(hb);
        g_Wl[(size_t)(n0 + n) * H + k0 + tx] =
            __bfloat16_as_ushort(__float2bfloat16_rn(x - __bfloat162float(hb)));
    }
}

// ---------------------------------------------------------------------------
// GEMM1: CTA 128x128, NOW BK=64 (halved barrier cadence, same fix that won
// -24% on gemm2), 2-stage cp.async, 128 KB dyn smem (occupancy 1 — proven
// insensitive in R8), 8 warps = 4(M) x 2(N), warp 32x64, hi/lo 3-pass.
// 128-B smem rows, swizzle c^(row&7) on 16B cols (validated in R14 gemm2).
// ---------------------------------------------------------------------------
#define BK1 64
#define TILE_B (128 * 128)        // 16 KB per tile
#define STAGE_B (4 * TILE_B)      // Ah, Al, Bh, Bl = 64 KB
#define SMEM_G1 (2 * STAGE_B)     // 128 KB

__global__ __launch_bounds__(256, 1) void gemm1_mma(const float* __restrict__ bias)
{
    extern __shared__ __align__(128) char smem[];
    const uint32_t sb = smem_to_u32(smem);
    const int tid = threadIdx.x;
    const int lane = tid & 31;
    const int wid = tid >> 5;
    const int wm = wid & 3;           // 0..3 (M)
    const int wn = wid >> 2;          // 0..1 (N)
    const int bm = blockIdx.y * 128;  // (b,s) tile
    const int bn = blockIdx.x * 128;  // h tile

    const unsigned short* srcs[4] = {g_Eh, g_El, g_Wh, g_Wl};

    float acc[2][8][4];
#pragma unroll
    for (int mt = 0; mt < 2; mt++)
#pragma unroll
        for (int nt = 0; nt < 8; nt++)
#pragma unroll
            for (int q = 0; q < 4; q++) acc[mt][nt][q] = 0.f;

    const int arow = lane & 15;
    const int half = lane >> 4;

    // 4096 16B-units per stage (1024 per tile: 128 rows x 8 cols), 16/thread.
#define G1_ISSUE(ch, stage)                                                    \
    do {                                                                       \
        const int _k0 = (ch) * BK1;                                            \
        _Pragma("unroll")                                                      \
        for (int _i = 0; _i < 16; _i++) {                                      \
            const int _u = tid + (_i << 8);                                    \
            const int _t = _u >> 10;                                           \
            const int _rem = _u & 1023;                                        \
            const int _row = _rem >> 3;                                        \
            const int _c = _rem & 7;                                           \
            const int _grow = ((_t < 2) ? bm : bn) + _row;                     \
            const void* _g = srcs[_t] + (size_t)_grow * H + _k0 + _c * 8;      \
            const uint32_t _sa = sb + (stage) * STAGE_B + _t * TILE_B          \
                + _row * 128 + (((_c) ^ (_row & 7)) << 4);                     \
            asm volatile("cp.async.cg.shared.global [%0], [%1], 16;"           \
                :: "r"(_sa), "l"(_g));                                         \
        }                                                                      \
        asm volatile("cp.async.commit_group;" ::: "memory");                   \
    } while (0)

    G1_ISSUE(0, 0);

    const int NCH = H / BK1;  // 16
    for (int ch = 0; ch < NCH; ++ch) {
        const int st = ch & 1;
        if (ch + 1 < NCH) {
            G1_ISSUE(ch + 1, st ^ 1);
            asm volatile("cp.async.wait_group 1;" ::: "memory");
        } else {
            asm volatile("cp.async.wait_group 0;" ::: "memory");
        }
        __syncthreads();

        const uint32_t base = sb + st * STAGE_B;
#pragma unroll
        for (int ks = 0; ks < 4; ++ks) {           // four k16 per BK=64
            const int cb = ks * 2 + half;          // 0..7
            uint32_t ah[2][4], al[2][4], bh[4][4], bl[4][4];
#pragma unroll
            for (int mt = 0; mt < 2; ++mt) {
                const int row = wm * 32 + mt * 16 + arow;
                const uint32_t off = row * 128 + ((cb ^ (row & 7)) << 4);
                LDSM4(ah[mt], base + 0 * TILE_B + off);
                LDSM4(al[mt], base + 1 * TILE_B + off);
            }
#pragma unroll
            for (int np = 0; np < 4; ++np) {
                const int row = wn * 64 + np * 16 + arow;
                const uint32_t off = row * 128 + ((cb ^ (row & 7)) << 4);
                LDSM4(bh[np], base + 2 * TILE_B + off);
                LDSM4(bl[np], base + 3 * TILE_B + off);
            }
#pragma unroll
            for (int np = 0; np < 4; ++np)
#pragma unroll
                for (int mt = 0; mt < 2; ++mt) {
                    MMA_BF16(acc[mt][2 * np],     ah[mt], bh[np][0], bh[np][2]);
                    MMA_BF16(acc[mt][2 * np + 1], ah[mt], bh[np][1], bh[np][3]);
                }
#pragma unroll
            for (int np = 0; np < 4; ++np)
#pragma unroll
                for (int mt = 0; mt < 2; ++mt) {
                    MMA_BF16(acc[mt][2 * np],     al[mt], bh[np][0], bh[np][2]);
                    MMA_BF16(acc[mt][2 * np + 1], al[mt], bh[np][1], bh[np][3]);
                }
#pragma unroll
            for (int np = 0; np < 4; ++np)
#pragma unroll
                for (int mt = 0; mt < 2; ++mt) {
                    MMA_BF16(acc[mt][2 * np],     ah[mt], bl[np][0], bl[np][2]);
                    MMA_BF16(acc[mt][2 * np + 1], ah[mt], bl[np][1], bl[np][3]);
                }
        }
        __syncthreads();
    }

    // Epilogue: tanh(D + bias[h]) split to bf16 hi/lo, stored [b][s][h].
    const int b_ = bm / S;
    const int s_base = (bm % S) + wm * 32 + (lane >> 2);
    const int n_base = bn + wn * 64;
#pragma unroll
    for (int mt = 0; mt < 2; ++mt) {
        const int s0 = s_base + mt * 16;
#pragma unroll
        for (int nt = 0; nt < 8; ++nt) {
            const int n0 = n_base + nt * 8 + 2 * (lane & 3);
            const float bv0 = bias[n0];
            const float bv1 = bias[n0 + 1];
            const size_t r0 = ((size_t)b_ * S + s0) * H + n0;
            const size_t r1 = ((size_t)b_ * S + s0 + 8) * H + n0;
            split_store2(&g_Ench[r0], &g_Encl[r0],
                         tanhf(acc[mt][nt][0] + bv0), tanhf(acc[mt][nt][1] + bv1));
            split_store2(&g_Ench[r1], &g_Encl[r1],
                         tanhf(acc[mt][nt][2] + bv0), tanhf(acc[mt][nt][3] + bv1));
        }
    }
}

// ---------------------------------------------------------------------------
// GEMM2 (R14 config — 15.8us): CTA 32(t)x64(s), BK=64, 2-stage cp.async,
// 4 warps = 2x2, warp 16x32, grid (8,8,4)=256 CTAs, 48 KB static smem.
// ---------------------------------------------------------------------------
#define BK2 64
#define G2_TA 4096                 // 32 rows x 128 B
#define G2_TB 8192                 // 64 rows x 128 B
#define G2STAGE (2 * G2_TA + 2 * G2_TB)   // 24 KB

__global__ __launch_bounds__(128, 2) void gemm2_mma(const float* __restrict__ ib)
{
    __shared__ __align__(128) char smem[2 * G2STAGE];   // 48 KB
    const uint32_t sb = smem_to_u32(smem);
    const int tid = threadIdx.x;
    const int lane = tid & 31;
    const int wid = tid >> 5;
    const int wm = wid & 1;           // 0..1 (t)
    const int wn = wid >> 1;          // 0..1 (s)
    const int b  = blockIdx.z;
    const int bt = blockIdx.y * 32;
    const int bs = blockIdx.x * 64;

    const unsigned short* srcA[2] = {
        g_Dech + (size_t)b * T * H, g_Decl + (size_t)b * T * H};
    const unsigned short* srcB[2] = {
        g_Ench + (size_t)b * S * H, g_Encl + (size_t)b * S * H};

    float acc[4][4];
#pragma unroll
    for (int nt = 0; nt < 4; nt++)
#pragma unroll
        for (int q = 0; q < 4; q++) acc[nt][q] = 0.f;

    const int arow = lane & 15;
    const int half = lane >> 4;

#define G2_ISSUE(ch, stage)                                                    \
    do {                                                                       \
        const int _k0 = (ch) * BK2;                                            \
        _Pragma("unroll")                                                      \
        for (int _i = 0; _i < 12; _i++) {                                      \
            const int _u = tid + (_i << 7);                                    \
            const unsigned short* _src;                                        \
            uint32_t _tb; int _rr, _gr;                                        \
            if (_u < 512) {                                                    \
                _src = srcA[_u >> 8];                                          \
                _tb = (_u < 256) ? 0u : (uint32_t)G2_TA;                       \
                _rr = (_u & 255) >> 3;                                         \
                _gr = bt + _rr;                                                \
            } else {                                                           \
                _src = srcB[(_u - 512) >> 9];                                  \
                _tb = (_u < 1024) ? (uint32_t)(2 * G2_TA)                      \
                                  : (uint32_t)(2 * G2_TA + G2_TB);             \
                _rr = (_u & 511) >> 3;                                         \
                _gr = bs + _rr;                                                \
            }                                                                  \
            const int _c = _u & 7;                                             \
            const void* _g = _src + (size_t)_gr * H + _k0 + _c * 8;            \
            const uint32_t _sa = sb + (stage) * G2STAGE + _tb                  \
                + _rr * 128 + (((_c) ^ (_rr & 7)) << 4);                       \
            asm volatile("cp.async.cg.shared.global [%0], [%1], 16;"           \
                :: "r"(_sa), "l"(_g));                                         \
        }                                                                      \
        asm volatile("cp.async.commit_group;" ::: "memory");                   \
    } while (0)

    G2_ISSUE(0, 0);

    const int NCH = H / BK2;   // 16
    for (int ch = 0; ch < NCH; ++ch) {
        const int st = ch & 1;
        if (ch + 1 < NCH) {
            G2_ISSUE(ch + 1, st ^ 1);
            asm volatile("cp.async.wait_group 1;" ::: "memory");
        } else {
            asm volatile("cp.async.wait_group 0;" ::: "memory");
        }
        __syncthreads();

        const uint32_t base = sb + st * G2STAGE;
#pragma unroll
        for (int ks = 0; ks < 4; ++ks) {
            const int cb = ks * 2 + half;
            uint32_t ah[4], al[4], bh[2][4], bl[2][4];
            {
                const int row = wm * 16 + arow;
                const uint32_t off = row * 128 + ((cb ^ (row & 7)) << 4);
                LDSM4(ah, base + off);
                LDSM4(al, base + G2_TA + off);
            }
#pragma unroll
            for (int np = 0; np < 2; ++np) {
                const int row = wn * 32 + np * 16 + arow;
                const uint32_t off = row * 128 + ((cb ^ (row & 7)) << 4);
                LDSM4(bh[np], base + 2 * G2_TA + off);
                LDSM4(bl[np], base + 2 * G2_TA + G2_TB + off);
            }
#pragma unroll
            for (int np = 0; np < 2; ++np) {
                MMA_BF16(acc[2 * np],     ah, bh[np][0], bh[np][2]);
                MMA_BF16(acc[2 * np + 1], ah, bh[np][1], bh[np][3]);
            }
#pragma unroll
            for (int np = 0; np < 2; ++np) {
                MMA_BF16(acc[2 * np],     al, bh[np][0], bh[np][2]);
                MMA_BF16(acc[2 * np + 1], al, bh[np][1], bh[np][3]);
            }
#pragma unroll
            for (int np = 0; np < 2; ++np) {
                MMA_BF16(acc[2 * np],     ah, bl[np][0], bl[np][2]);
                MMA_BF16(acc[2 * np + 1], ah, bl[np][1], bl[np][3]);
            }
        }
        __syncthreads();
    }

    // Epilogue: + input_bias, fp32 scores.
    const int t0 = bt + wm * 16 + (lane >> 2);
    const int s_col = bs + wn * 32;
#pragma unroll
    for (int nt = 0; nt < 4; ++nt) {
        const int s = s_col + nt * 8 + 2 * (lane & 3);
        const float b0 = ib[b * S + s];
        const float b1 = ib[b * S + s + 1];
        float2 v0 = make_float2(acc[nt][0] + b0, acc[nt][1] + b1);
        float2 v1 = make_float2(acc[nt][2] + b0, acc[nt][3] + b1);
        *(float2*)&g_scores[((size_t)b * T + t0) * S + s] = v0;
        *(float2*)&g_scores[((size_t)b * T + t0 + 8) * S + s] = v1;
    }
}

// ---------------------------------------------------------------------------
// Kernel 3: 512 threads — zero vocab slice, softmax over S (1 elt/thread),
// scatter-add.
// ---------------------------------------------------------------------------
__global__ __launch_bounds__(512) void softmax_scatter(
    const int* __restrict__ ids, float* __restrict__ out)
{
    const int bt = blockIdx.x;
    const int b = bt / T;
    const int tid = threadIdx.x;

    const float* row = &g_scores[(size_t)bt * S];
    float* orow = out + (size_t)bt * V;

    const float4 z = make_float4(0.f, 0.f, 0.f, 0.f);
    float4* orow4 = (float4*)orow;
#pragma unroll 4
    for (int i = tid; i < V / 4; i += 512) orow4[i] = z;

    __shared__ float red[16];

    float v = row[tid];

    float m = v;
#pragma unroll
    for (int o = 16; o > 0; o >>= 1)
        m = fmaxf(m, __shfl_xor_sync(0xFFFFFFFFu, m, o));
    if ((tid & 31) == 0) red[tid >> 5] = m;
    __syncthreads();
    if (tid < 16) {
        float t = red[tid];
#pragma unroll
        for (int o = 8; o > 0; o >>= 1)
            t = fmaxf(t, __shfl_xor_sync(0xFFFFu, t, o));
        red[tid] = t;
    }
    __syncthreads();
    const float mx = red[0];

    float e = expf(v - mx);
    float s = e;
#pragma unroll
    for (int o = 16; o > 0; o >>= 1)
        s += __shfl_xor_sync(0xFFFFFFFFu, s, o);
    __syncthreads();
    if ((tid & 31) == 0) red[tid >> 5] = s;
    __syncthreads();
    if (tid < 16) {
        float t = red[tid];
#pragma unroll
        for (int o = 8; o > 0; o >>= 1)
            t += __shfl_xor_sync(0xFFFFu, t, o);
        red[tid] = t;
    }
    __syncthreads();
    const float inv = 1.0f / red[0];

    atomicAdd(&orow[ids[b * S + tid]], e * inv);
}

// ---------------------------------------------------------------------------
extern "C" void kernel_launch(void* const* d_in, const int* in_sizes, int n_in,
                              void* d_out, int out_size)
{
    const int*   inputs = (const int*)d_in[0];    // [B,S] int32
    const float* E      = (const float*)d_in[1];  // [B,S,H]
    const float* Dec    = (const float*)d_in[2];  // [B,T,H]
    const float* ib     = (const float*)d_in[3];  // [B,S]
    const float* Wp     = (const float*)d_in[4];  // [H,H]
    const float* bp     = (const float*)d_in[5];  // [H]
    float* out = (float*)d_out;                   // [B,T,V]

    static bool attr_set = false;
    if (!attr_set) {
        cudaFuncSetAttribute(gemm1_mma,
                             cudaFuncAttributeMaxDynamicSharedMemorySize, SMEM_G1);
        attr_set = true;
    }

    convert_splits<<<(E_F4 + D_F4) / 256, 256>>>(E, Dec);
    convert_W<<<dim3(H / 32, H / 32), 256>>>(Wp);

    dim3 g1(H / 128, M1 / 128);                   // (8, 16) = 128 CTAs
    gemm1_mma<<<g1, 256, SMEM_G1>>>(bp);

    dim3 g2(S / 64, T / 32, B);                   // (8, 8, 4) = 256 CTAs
    gemm2_mma<<<g2, 128>>>(ib);

    softmax_scatter<<<B * T, 512>>>(inputs, out);
}

// round 16
// speedup vs baseline: 1.1175x; 1.0451x over previous
#include <cuda_runtime.h>
#include <cuda_bf16.h>
#include <math.h>
#include <cstdint>

// Problem constants (fixed shapes)
#define B 4
#define S 512
#define T 256
#define H 1024
#define V 32000
#define M1 (B * S)   // 2048

// Scratch (device globals — no allocations allowed)
__device__ float g_scores[B * T * S];        // [b][t][s], 2 MB
__device__ unsigned short g_Eh[M1 * H];      // bf16 hi of E   [M,K]
__device__ unsigned short g_El[M1 * H];      // bf16 lo of E   [M,K]
__device__ unsigned short g_Wh[H * H];       // bf16 hi of W^T [N,K]
__device__ unsigned short g_Wl[H * H];       // bf16 lo of W^T [N,K]
__device__ unsigned short g_Ench[B * S * H]; // bf16 hi of enc [b][s][h]
__device__ unsigned short g_Encl[B * S * H]; // bf16 lo of enc [b][s][h]
__device__ unsigned short g_Dech[B * T * H]; // bf16 hi of dec [b][t][h]
__device__ unsigned short g_Decl[B * T * H]; // bf16 lo of dec [b][t][h]

// ---------------------------------------------------------------------------
// Arch-generic tensor-core primitives (legal on plain sm_103 target)
// ---------------------------------------------------------------------------
#define LDSM4(r, a)                                                            \
    asm volatile("ldmatrix.sync.aligned.m8n8.x4.shared.b16 {%0,%1,%2,%3}, [%4];" \
        : "=r"((r)[0]), "=r"((r)[1]), "=r"((r)[2]), "=r"((r)[3]) : "r"(a))

#define MMA_BF16(d, a, b0, b1)                                                 \
    asm volatile(                                                              \
        "mma.sync.aligned.m16n8k16.row.col.f32.bf16.bf16.f32 "                 \
        "{%0,%1,%2,%3}, {%4,%5,%6,%7}, {%8,%9}, {%0,%1,%2,%3};"                \
        : "+f"((d)[0]), "+f"((d)[1]), "+f"((d)[2]), "+f"((d)[3])               \
        : "r"((a)[0]), "r"((a)[1]), "r"((a)[2]), "r"((a)[3]),                  \
          "r"(b0), "r"(b1))

__device__ __forceinline__ uint32_t smem_to_u32(const void* p) {
    uint32_t a;
    asm("{ .reg .u64 t; cvta.to.shared.u64 t, %1; cvt.u32.u64 %0, t; }"
        : "=r"(a) : "l"(p));
    return a;
}

__device__ __forceinline__ void split_store2(
    unsigned short* hp, unsigned short* lp, float v0, float v1)
{
    __nv_bfloat16 h0 = __float2bfloat16_rn(v0);
    __nv_bfloat16 h1 = __float2bfloat16_rn(v1);
    unsigned short l0 = __bfloat16_as_ushort(__float2bfloat16_rn(v0 - __bfloat162float(h0)));
    unsigned short l1 = __bfloat16_as_ushort(__float2bfloat16_rn(v1 - __bfloat162float(h1)));
    *(uint32_t*)hp = (uint32_t)__bfloat16_as_ushort(h0) |
                     ((uint32_t)__bfloat16_as_ushort(h1) << 16);
    *(uint32_t*)lp = (uint32_t)l0 | ((uint32_t)l1 << 16);
}

// ---------------------------------------------------------------------------
// Merged converter: E + Dec hi/lo splits AND W transpose-split, one launch.
// Blocks [0, NB_SPLIT) do the elementwise splits; blocks [NB_SPLIT, +1024)
// do the W tiled transpose.
// ---------------------------------------------------------------------------
#define E_F4 (M1 * H / 4)          // 524288
#define D_F4 (B * T * H / 4)       // 262144
#define NB_SPLIT ((E_F4 + D_F4) / 256)   // 3072
#define NB_W 1024                         // (H/32)*(H/32)
#define NB_CONV (NB_SPLIT + NB_W)         // 4096

__global__ __launch_bounds__(256) void convert_all(
    const float* __restrict__ E, const float* __restrict__ Dec,
    const float* __restrict__ W)
{
    if (blockIdx.x < NB_SPLIT) {
        const int idx = blockIdx.x * 256 + threadIdx.x;
        const float* src;
        unsigned short *hi, *lo;
        int j;
        if (idx < E_F4) {
            src = E; hi = g_Eh; lo = g_El; j = idx;
        } else {
            src = Dec; hi = g_Dech; lo = g_Decl; j = idx - E_F4;
        }
        const float4 v = ((const float4*)src)[j];
        ushort4 h, l;
        const float* vf = (const float*)&v;
        unsigned short* hp = (unsigned short*)&h;
        unsigned short* lp = (unsigned short*)&l;
#pragma unroll
        for (int i = 0; i < 4; i++) {
            __nv_bfloat16 hb = __float2bfloat16_rn(vf[i]);
            hp[i] = __bfloat16_as_ushort(hb);
            lp[i] = __bfloat16_as_ushort(__float2bfloat16_rn(vf[i] - __bfloat162float(hb)));
        }
        ((ushort4*)hi)[j] = h;
        ((ushort4*)lo)[j] = l;
    } else {
        __shared__ float t[32][33];
        const int wb = blockIdx.x - NB_SPLIT;     // 0..1023
        const int k0 = (wb & 31) * 32;
        const int n0 = (wb >> 5) * 32;
        const int tx = threadIdx.x & 31;
        const int ty = threadIdx.x >> 5;
#pragma unroll
        for (int r = 0; r < 4; r++) {
            const int k = ty + r * 8;
            t[k][tx] = W[(size_t)(k0 + k) * H + n0 + tx];
        }
        __syncthreads();
#pragma unroll
        for (int r = 0; r < 4; r++) {
            const int n = ty + r * 8;
            const float x = t[tx][n];
            __nv_bfloat16 hb = __float2bfloat16_rn(x);
            g_Wh[(size_t)(n0 + n) * H + k0 + tx] = __bfloat16_as_ushort(hb);
            g_Wl[(size_t)(n0 + n) * H + k0 + tx] =
                __bfloat16_as_ushort(__float2bfloat16_rn(x - __bfloat162float(hb)));
        }
    }
}

// ---------------------------------------------------------------------------
// GEMM1 (R15 config): CTA 128x128, BK=64, 2-stage cp.async, 128 KB dyn smem,
// 8 warps = 4(M) x 2(N), warp 32x64, hi/lo 3-pass, swizzle c^(row&7).
// ---------------------------------------------------------------------------
#define BK1 64
#define TILE_B (128 * 128)        // 16 KB per tile
#define STAGE_B (4 * TILE_B)      // Ah, Al, Bh, Bl = 64 KB
#define SMEM_G1 (2 * STAGE_B)     // 128 KB

__global__ __launch_bounds__(256, 1) void gemm1_mma(const float* __restrict__ bias)
{
    extern __shared__ __align__(128) char smem[];
    const uint32_t sb = smem_to_u32(smem);
    const int tid = threadIdx.x;
    const int lane = tid & 31;
    const int wid = tid >> 5;
    const int wm = wid & 3;           // 0..3 (M)
    const int wn = wid >> 2;          // 0..1 (N)
    const int bm = blockIdx.y * 128;  // (b,s) tile
    const int bn = blockIdx.x * 128;  // h tile

    const unsigned short* srcs[4] = {g_Eh, g_El, g_Wh, g_Wl};

    float acc[2][8][4];
#pragma unroll
    for (int mt = 0; mt < 2; mt++)
#pragma unroll
        for (int nt = 0; nt < 8; nt++)
#pragma unroll
            for (int q = 0; q < 4; q++) acc[mt][nt][q] = 0.f;

    const int arow = lane & 15;
    const int half = lane >> 4;

#define G1_ISSUE(ch, stage)                                                    \
    do {                                                                       \
        const int _k0 = (ch) * BK1;                                            \
        _Pragma("unroll")                                                      \
        for (int _i = 0; _i < 16; _i++) {                                      \
            const int _u = tid + (_i << 8);                                    \
            const int _t = _u >> 10;                                           \
            const int _rem = _u & 1023;                                        \
            const int _row = _rem >> 3;                                        \
            const int _c = _rem & 7;                                           \
            const int _grow = ((_t < 2) ? bm : bn) + _row;                     \
            const void* _g = srcs[_t] + (size_t)_grow * H + _k0 + _c * 8;      \
            const uint32_t _sa = sb + (stage) * STAGE_B + _t * TILE_B          \
                + _row * 128 + (((_c) ^ (_row & 7)) << 4);                     \
            asm volatile("cp.async.cg.shared.global [%0], [%1], 16;"           \
                :: "r"(_sa), "l"(_g));                                         \
        }                                                                      \
        asm volatile("cp.async.commit_group;" ::: "memory");                   \
    } while (0)

    G1_ISSUE(0, 0);

    const int NCH = H / BK1;  // 16
    for (int ch = 0; ch < NCH; ++ch) {
        const int st = ch & 1;
        if (ch + 1 < NCH) {
            G1_ISSUE(ch + 1, st ^ 1);
            asm volatile("cp.async.wait_group 1;" ::: "memory");
        } else {
            asm volatile("cp.async.wait_group 0;" ::: "memory");
        }
        __syncthreads();

        const uint32_t base = sb + st * STAGE_B;
#pragma unroll
        for (int ks = 0; ks < 4; ++ks) {
            const int cb = ks * 2 + half;
            uint32_t ah[2][4], al[2][4], bh[4][4], bl[4][4];
#pragma unroll
            for (int mt = 0; mt < 2; ++mt) {
                const int row = wm * 32 + mt * 16 + arow;
                const uint32_t off = row * 128 + ((cb ^ (row & 7)) << 4);
                LDSM4(ah[mt], base + 0 * TILE_B + off);
                LDSM4(al[mt], base + 1 * TILE_B + off);
            }
#pragma unroll
            for (int np = 0; np < 4; ++np) {
                const int row = wn * 64 + np * 16 + arow;
                const uint32_t off = row * 128 + ((cb ^ (row & 7)) << 4);
                LDSM4(bh[np], base + 2 * TILE_B + off);
                LDSM4(bl[np], base + 3 * TILE_B + off);
            }
#pragma unroll
            for (int np = 0; np < 4; ++np)
#pragma unroll
                for (int mt = 0; mt < 2; ++mt) {
                    MMA_BF16(acc[mt][2 * np],     ah[mt], bh[np][0], bh[np][2]);
                    MMA_BF16(acc[mt][2 * np + 1], ah[mt], bh[np][1], bh[np][3]);
                }
#pragma unroll
            for (int np = 0; np < 4; ++np)
#pragma unroll
                for (int mt = 0; mt < 2; ++mt) {
                    MMA_BF16(acc[mt][2 * np],     al[mt], bh[np][0], bh[np][2]);
                    MMA_BF16(acc[mt][2 * np + 1], al[mt], bh[np][1], bh[np][3]);
                }
#pragma unroll
            for (int np = 0; np < 4; ++np)
#pragma unroll
                for (int mt = 0; mt < 2; ++mt) {
                    MMA_BF16(acc[mt][2 * np],     ah[mt], bl[np][0], bl[np][2]);
                    MMA_BF16(acc[mt][2 * np + 1], ah[mt], bl[np][1], bl[np][3]);
                }
        }
        __syncthreads();
    }

    // Epilogue: tanh(D + bias[h]) split to bf16 hi/lo, stored [b][s][h].
    const int b_ = bm / S;
    const int s_base = (bm % S) + wm * 32 + (lane >> 2);
    const int n_base = bn + wn * 64;
#pragma unroll
    for (int mt = 0; mt < 2; ++mt) {
        const int s0 = s_base + mt * 16;
#pragma unroll
        for (int nt = 0; nt < 8; ++nt) {
            const int n0 = n_base + nt * 8 + 2 * (lane & 3);
            const float bv0 = bias[n0];
            const float bv1 = bias[n0 + 1];
            const size_t r0 = ((size_t)b_ * S + s0) * H + n0;
            const size_t r1 = ((size_t)b_ * S + s0 + 8) * H + n0;
            split_store2(&g_Ench[r0], &g_Encl[r0],
                         tanhf(acc[mt][nt][0] + bv0), tanhf(acc[mt][nt][1] + bv1));
            split_store2(&g_Ench[r1], &g_Encl[r1],
                         tanhf(acc[mt][nt][2] + bv0), tanhf(acc[mt][nt][3] + bv1));
        }
    }
}

// ---------------------------------------------------------------------------
// GEMM2 (R14/R15 config — 15.8us): CTA 32(t)x64(s), BK=64, 2-stage cp.async,
// 4 warps = 2x2, warp 16x32, grid (8,8,4)=256 CTAs, 48 KB static smem.
// ---------------------------------------------------------------------------
#define BK2 64
#define G2_TA 4096                 // 32 rows x 128 B
#define G2_TB 8192                 // 64 rows x 128 B
#define G2STAGE (2 * G2_TA + 2 * G2_TB)   // 24 KB

__global__ __launch_bounds__(128, 2) void gemm2_mma(const float* __restrict__ ib)
{
    __shared__ __align__(128) char smem[2 * G2STAGE];   // 48 KB
    const uint32_t sb = smem_to_u32(smem);
    const int tid = threadIdx.x;
    const int lane = tid & 31;
    const int wid = tid >> 5;
    const int wm = wid & 1;           // 0..1 (t)
    const int wn = wid >> 1;          // 0..1 (s)
    const int b  = blockIdx.z;
    const int bt = blockIdx.y * 32;
    const int bs = blockIdx.x * 64;

    const unsigned short* srcA[2] = {
        g_Dech + (size_t)b * T * H, g_Decl + (size_t)b * T * H};
    const unsigned short* srcB[2] = {
        g_Ench + (size_t)b * S * H, g_Encl + (size_t)b * S * H};

    float acc[4][4];
#pragma unroll
    for (int nt = 0; nt < 4; nt++)
#pragma unroll
        for (int q = 0; q < 4; q++) acc[nt][q] = 0.f;

    const int arow = lane & 15;
    const int half = lane >> 4;

#define G2_ISSUE(ch, stage)                                                    \
    do {                                                                       \
        const int _k0 = (ch) * BK2;                                            \
        _Pragma("unroll")                                                      \
        for (int _i = 0; _i < 12; _i++) {                                      \
            const int _u = tid + (_i << 7);                                    \
            const unsigned short* _src;                                        \
            uint32_t _tb; int _rr, _gr;                                        \
            if (_u < 512) {                                                    \
                _src = srcA[_u >> 8];                                          \
                _tb = (_u < 256) ? 0u : (uint32_t)G2_TA;                       \
                _rr = (_u & 255) >> 3;                                         \
                _gr = bt + _rr;                                                \
            } else {                                                           \
                _src = srcB[(_u - 512) >> 9];                                  \
                _tb = (_u < 1024) ? (uint32_t)(2 * G2_TA)                      \
                                  : (uint32_t)(2 * G2_TA + G2_TB);             \
                _rr = (_u & 511) >> 3;                                         \
                _gr = bs + _rr;                                                \
            }                                                                  \
            const int _c = _u & 7;                                             \
            const void* _g = _src + (size_t)_gr * H + _k0 + _c * 8;            \
            const uint32_t _sa = sb + (stage) * G2STAGE + _tb                  \
                + _rr * 128 + (((_c) ^ (_rr & 7)) << 4);                       \
            asm volatile("cp.async.cg.shared.global [%0], [%1], 16;"           \
                :: "r"(_sa), "l"(_g));                                         \
        }                                                                      \
        asm volatile("cp.async.commit_group;" ::: "memory");                   \
    } while (0)

    G2_ISSUE(0, 0);

    const int NCH = H / BK2;   // 16
    for (int ch = 0; ch < NCH; ++ch) {
        const int st = ch & 1;
        if (ch + 1 < NCH) {
            G2_ISSUE(ch + 1, st ^ 1);
            asm volatile("cp.async.wait_group 1;" ::: "memory");
        } else {
            asm volatile("cp.async.wait_group 0;" ::: "memory");
        }
        __syncthreads();

        const uint32_t base = sb + st * G2STAGE;
#pragma unroll
        for (int ks = 0; ks < 4; ++ks) {
            const int cb = ks * 2 + half;
            uint32_t ah[4], al[4], bh[2][4], bl[2][4];
            {
                const int row = wm * 16 + arow;
                const uint32_t off = row * 128 + ((cb ^ (row & 7)) << 4);
                LDSM4(ah, base + off);
                LDSM4(al, base + G2_TA + off);
            }
#pragma unroll
            for (int np = 0; np < 2; ++np) {
                const int row = wn * 32 + np * 16 + arow;
                const uint32_t off = row * 128 + ((cb ^ (row & 7)) << 4);
                LDSM4(bh[np], base + 2 * G2_TA + off);
                LDSM4(bl[np], base + 2 * G2_TA + G2_TB + off);
            }
#pragma unroll
            for (int np = 0; np < 2; ++np) {
                MMA_BF16(acc[2 * np],     ah, bh[np][0], bh[np][2]);
                MMA_BF16(acc[2 * np + 1], ah, bh[np][1], bh[np][3]);
            }
#pragma unroll
            for (int np = 0; np < 2; ++np) {
                MMA_BF16(acc[2 * np],     al, bh[np][0], bh[np][2]);
                MMA_BF16(acc[2 * np + 1], al, bh[np][1], bh[np][3]);
            }
#pragma unroll
            for (int np = 0; np < 2; ++np) {
                MMA_BF16(acc[2 * np],     ah, bl[np][0], bl[np][2]);
                MMA_BF16(acc[2 * np + 1], ah, bl[np][1], bl[np][3]);
            }
        }
        __syncthreads();
    }

    // Epilogue: + input_bias, fp32 scores.
    const int t0 = bt + wm * 16 + (lane >> 2);
    const int s_col = bs + wn * 32;
#pragma unroll
    for (int nt = 0; nt < 4; ++nt) {
        const int s = s_col + nt * 8 + 2 * (lane & 3);
        const float b0 = ib[b * S + s];
        const float b1 = ib[b * S + s + 1];
        float2 v0 = make_float2(acc[nt][0] + b0, acc[nt][1] + b1);
        float2 v1 = make_float2(acc[nt][2] + b0, acc[nt][3] + b1);
        *(float2*)&g_scores[((size_t)b * T + t0) * S + s] = v0;
        *(float2*)&g_scores[((size_t)b * T + t0 + 8) * S + s] = v1;
    }
}

// ---------------------------------------------------------------------------
// Kernel 3: 512 threads — score load hoisted above the zero loop (hides its
// DRAM latency under the zeroing stores), zero vocab slice (unroll 8),
// softmax over S (1 elt/thread), scatter-add.
// ---------------------------------------------------------------------------
__global__ __launch_bounds__(512) void softmax_scatter(
    const int* __restrict__ ids, float* __restrict__ out)
{
    const int bt = blockIdx.x;
    const int b = bt / T;
    const int tid = threadIdx.x;

    const float* row = &g_scores[(size_t)bt * S];
    float* orow = out + (size_t)bt * V;

    // Issue the score + id loads FIRST so their latency hides under zeroing.
    const float v = row[tid];
    const int my_id = ids[b * S + tid];

    // Zero the vocab slice (8000 float4 over 512 threads)
    const float4 z = make_float4(0.f, 0.f, 0.f, 0.f);
    float4* orow4 = (float4*)orow;
#pragma unroll 8
    for (int i = tid; i < V / 4; i += 512) orow4[i] = z;

    __shared__ float red[16];

    // Max reduce
    float m = v;
#pragma unroll
    for (int o = 16; o > 0; o >>= 1)
        m = fmaxf(m, __shfl_xor_sync(0xFFFFFFFFu, m, o));
    if ((tid & 31) == 0) red[tid >> 5] = m;
    __syncthreads();
    if (tid < 16) {
        float t = red[tid];
#pragma unroll
        for (int o = 8; o > 0; o >>= 1)
            t = fmaxf(t, __shfl_xor_sync(0xFFFFu, t, o));
        red[tid] = t;
    }
    __syncthreads();
    const float mx = red[0];

    // Exp + sum reduce
    float e = expf(v - mx);
    float s = e;
#pragma unroll
    for (int o = 16; o > 0; o >>= 1)
        s += __shfl_xor_sync(0xFFFFFFFFu, s, o);
    __syncthreads();
    if ((tid & 31) == 0) red[tid >> 5] = s;
    __syncthreads();
    if (tid < 16) {
        float t = red[tid];
#pragma unroll
        for (int o = 8; o > 0; o >>= 1)
            t += __shfl_xor_sync(0xFFFFu, t, o);
        red[tid] = t;
    }
    __syncthreads();
    const float inv = 1.0f / red[0];

    atomicAdd(&orow[my_id], e * inv);
}

// ---------------------------------------------------------------------------
extern "C" void kernel_launch(void* const* d_in, const int* in_sizes, int n_in,
                              void* d_out, int out_size)
{
    const int*   inputs = (const int*)d_in[0];    // [B,S] int32
    const float* E      = (const float*)d_in[1];  // [B,S,H]
    const float* Dec    = (const float*)d_in[2];  // [B,T,H]
    const float* ib     = (const float*)d_in[3];  // [B,S]
    const float* Wp     = (const float*)d_in[4];  // [H,H]
    const float* bp     = (const float*)d_in[5];  // [H]
    float* out = (float*)d_out;                   // [B,T,V]

    static bool attr_set = false;
    if (!attr_set) {
        cudaFuncSetAttribute(gemm1_mma,
                             cudaFuncAttributeMaxDynamicSharedMemorySize, SMEM_G1);
        attr_set = true;
    }

    convert_all<<<NB_CONV, 256>>>(E, Dec, Wp);    // one launch for all converts

    dim3 g1(H / 128, M1 / 128);                   // (8, 16) = 128 CTAs
    gemm1_mma<<<g1, 256, SMEM_G1>>>(bp);

    dim3 g2(S / 64, T / 32, B);                   // (8, 8, 4) = 256 CTAs
    gemm2_mma<<<g2, 128>>>(ib);

    softmax_scatter<<<B * T, 512>>>(inputs, out);
}